// round 6
// baseline (speedup 1.0000x reference)
#include <cuda_runtime.h>

#define Nn   100000
#define Ee   1600000
#define F    128          // IN_F == HIDDEN
#define C2T  80           // HEADS * N_CLASSES
#define NCls 40
#define NEG  0.2f
#define EPS  1e-5f

// ---------------- scratch (static device globals; no runtime alloc) ----------
__device__ float g_h1[Nn * F];
__device__ float g_out1[Nn * F];
__device__ float g_h2[Nn * C2T];
__device__ float g_out2[Nn * C2T];

__device__ float g_asrc1[Nn * 2], g_adst1[Nn * 2], g_aself1[Nn * 2], g_den1[Nn * 2];
__device__ float g_asrc2[Nn * 2], g_adst2[Nn * 2], g_aself2[Nn * 2], g_den2[Nn * 2];
__device__ int   g_amax1[Nn * 2], g_amax2[Nn * 2];

__device__ float g_alp1[Ee * 2], g_alp2[Ee * 2];

__device__ float g_bns[F], g_bnq[F], g_scale[F], g_shift[F];

// ---------------- helpers ----------------------------------------------------
__device__ __forceinline__ int   fenc(float f) { int i = __float_as_int(f); return i >= 0 ? i : i ^ 0x7FFFFFFF; }
__device__ __forceinline__ float fdec(int i)   { return __int_as_float(i >= 0 ? i : i ^ 0x7FFFFFFF); }
__device__ __forceinline__ float lrelu(float x){ return x > 0.f ? x : NEG * x; }

__device__ __forceinline__ void red4(float* p, float a, float b, float c, float d) {
    asm volatile("red.global.add.v4.f32 [%0], {%1,%2,%3,%4};"
                 :: "l"(p), "f"(a), "f"(b), "f"(c), "f"(d) : "memory");
}

template<int L> __device__ __forceinline__ float* P_asrc()  { return L == 1 ? g_asrc1  : g_asrc2;  }
template<int L> __device__ __forceinline__ float* P_adst()  { return L == 1 ? g_adst1  : g_adst2;  }
template<int L> __device__ __forceinline__ float* P_aself() { return L == 1 ? g_aself1 : g_aself2; }
template<int L> __device__ __forceinline__ float* P_den()   { return L == 1 ? g_den1   : g_den2;   }
template<int L> __device__ __forceinline__ int*   P_amax()  { return L == 1 ? g_amax1  : g_amax2;  }
template<int L> __device__ __forceinline__ float* P_alp()   { return L == 1 ? g_alp1   : g_alp2;   }

// ---------------- zero scratch -----------------------------------------------
__global__ void k_zero() {
    int i = blockIdx.x * blockDim.x + threadIdx.x;
    int stride = gridDim.x * blockDim.x;
    for (int t = i; t < Nn * F;   t += stride) g_out1[t] = 0.f;
    for (int t = i; t < Nn * C2T; t += stride) g_out2[t] = 0.f;
    for (int t = i; t < Nn * 2;   t += stride) {
        g_asrc1[t] = 0.f; g_adst1[t] = 0.f; g_asrc2[t] = 0.f; g_adst2[t] = 0.f;
    }
    if (i < F) { g_bns[i] = 0.f; g_bnq[i] = 0.f; }
}

// ---------------- GEMM1: h1 = x @ W1, fused attention dot products -----------
__global__ __launch_bounds__(256)
void k_gemm1(const float* __restrict__ x, const float* __restrict__ W,
             const float* __restrict__ attS, const float* __restrict__ attD) {
    __shared__ float xs[32][64];    // [k][m]
    __shared__ float ws[32][128];   // [k][n]
    int tid = threadIdx.x;
    int rowBase = blockIdx.x * 64;
    int tx = tid & 15, ty = tid >> 4;
    float acc[4][8] = {};

    for (int k0 = 0; k0 < F; k0 += 32) {
        // x tile: 64 rows x 32 k (transposed into smem)
        #pragma unroll
        for (int l = 0; l < 2; l++) {
            int v = tid + l * 256;          // 0..511
            int r = v >> 3, kq = v & 7;
            int grow = rowBase + r;
            float4 xv = make_float4(0.f, 0.f, 0.f, 0.f);
            if (grow < Nn) xv = *(const float4*)&x[grow * F + k0 + kq * 4];
            int kk = kq * 4;
            xs[kk + 0][r] = xv.x; xs[kk + 1][r] = xv.y;
            xs[kk + 2][r] = xv.z; xs[kk + 3][r] = xv.w;
        }
        // W tile: 32 k x 128 n
        #pragma unroll
        for (int l = 0; l < 4; l++) {
            int v = tid + l * 256;          // 0..1023
            int kk = v >> 5, nq = v & 31;
            *(float4*)&ws[kk][nq * 4] = *(const float4*)&W[(k0 + kk) * F + nq * 4];
        }
        __syncthreads();
        #pragma unroll
        for (int kk = 0; kk < 32; kk++) {
            float4 a  = *(float4*)&xs[kk][ty * 4];
            float4 b0 = *(float4*)&ws[kk][tx * 8];
            float4 b1 = *(float4*)&ws[kk][tx * 8 + 4];
            acc[0][0] += a.x * b0.x; acc[0][1] += a.x * b0.y; acc[0][2] += a.x * b0.z; acc[0][3] += a.x * b0.w;
            acc[0][4] += a.x * b1.x; acc[0][5] += a.x * b1.y; acc[0][6] += a.x * b1.z; acc[0][7] += a.x * b1.w;
            acc[1][0] += a.y * b0.x; acc[1][1] += a.y * b0.y; acc[1][2] += a.y * b0.z; acc[1][3] += a.y * b0.w;
            acc[1][4] += a.y * b1.x; acc[1][5] += a.y * b1.y; acc[1][6] += a.y * b1.z; acc[1][7] += a.y * b1.w;
            acc[2][0] += a.z * b0.x; acc[2][1] += a.z * b0.y; acc[2][2] += a.z * b0.z; acc[2][3] += a.z * b0.w;
            acc[2][4] += a.z * b1.x; acc[2][5] += a.z * b1.y; acc[2][6] += a.z * b1.z; acc[2][7] += a.z * b1.w;
            acc[3][0] += a.w * b0.x; acc[3][1] += a.w * b0.y; acc[3][2] += a.w * b0.z; acc[3][3] += a.w * b0.w;
            acc[3][4] += a.w * b1.x; acc[3][5] += a.w * b1.y; acc[3][6] += a.w * b1.z; acc[3][7] += a.w * b1.w;
        }
        __syncthreads();
    }
    int head = tx >> 3;     // 8 cols per tx, head boundary at col 64
    #pragma unroll
    for (int r = 0; r < 4; r++) {
        int grow = rowBase + ty * 4 + r;
        if (grow < Nn) {
            *(float4*)&g_h1[grow * F + tx * 8]     = make_float4(acc[r][0], acc[r][1], acc[r][2], acc[r][3]);
            *(float4*)&g_h1[grow * F + tx * 8 + 4] = make_float4(acc[r][4], acc[r][5], acc[r][6], acc[r][7]);
            float as = 0.f, ad = 0.f;
            #pragma unroll
            for (int j = 0; j < 8; j++) {
                int col = tx * 8 + j;
                as += acc[r][j] * attS[col];
                ad += acc[r][j] * attD[col];
            }
            atomicAdd(&g_asrc1[grow * 2 + head], as);
            atomicAdd(&g_adst1[grow * 2 + head], ad);
        }
    }
}

// ---------------- attention pipeline (shared by both layers) -----------------
template<int L>
__global__ void k_pre() {                 // self-loop alpha; seed amax; zero denom
    int t = blockIdx.x * blockDim.x + threadIdx.x;
    if (t >= 2 * Nn) return;
    float al = lrelu(P_asrc<L>()[t] + P_adst<L>()[t]);
    P_aself<L>()[t] = al;
    P_amax<L>()[t]  = fenc(al);
    P_den<L>()[t]   = 0.f;
}

template<int L>
__global__ void k_emax(const int* __restrict__ src, const int* __restrict__ dst) {
    int t = blockIdx.x * blockDim.x + threadIdx.x;
    if (t >= 2 * Ee) return;
    int e = t >> 1, h = t & 1;
    int s = __ldg(&src[e]), d = __ldg(&dst[e]);
    float al = lrelu(P_asrc<L>()[s * 2 + h] + P_adst<L>()[d * 2 + h]);
    P_alp<L>()[t] = al;
    atomicMax(&P_amax<L>()[d * 2 + h], fenc(al));
}

template<int L>
__global__ void k_mid() {                 // denom starts with the self-loop term
    int t = blockIdx.x * blockDim.x + threadIdx.x;
    if (t >= 2 * Nn) return;
    P_den<L>()[t] = __expf(P_aself<L>()[t] - fdec(P_amax<L>()[t]));
}

template<int L>
__global__ void k_esum(const int* __restrict__ dst) {
    int t = blockIdx.x * blockDim.x + threadIdx.x;
    if (t >= 2 * Ee) return;
    int e = t >> 1, h = t & 1;
    int d = __ldg(&dst[e]);
    float ev = __expf(P_alp<L>()[t] - fdec(P_amax<L>()[d * 2 + h]));
    P_alp<L>()[t] = ev;
    atomicAdd(&P_den<L>()[d * 2 + h], ev);
}

// ---------------- edge messages: layer 1 (warp per edge, 128 floats) ---------
__global__ void k_msg1(const int* __restrict__ src, const int* __restrict__ dst) {
    int warp = (blockIdx.x * blockDim.x + threadIdx.x) >> 5;
    int lane = threadIdx.x & 31;
    if (warp >= Ee) return;
    int s = __ldg(&src[warp]);
    int d = __ldg(&dst[warp]);
    int h = lane >> 4;                      // lanes 0..15 head0, 16..31 head1
    float w = g_alp1[warp * 2 + h] / g_den1[d * 2 + h];
    float4 v = ((const float4*)&g_h1[s * F])[lane];
    red4(&g_out1[d * F + lane * 4], v.x * w, v.y * w, v.z * w, v.w * w);
}

// ---------------- edge messages: layer 2 (20 threads per edge, 80 floats) ----
__global__ void k_msg2(const int* __restrict__ src, const int* __restrict__ dst) {
    int t = blockIdx.x * blockDim.x + threadIdx.x;
    if (t >= Ee * 20) return;
    int e = t / 20, q = t % 20;
    int h = q / 10;
    int s = __ldg(&src[e]);
    int d = __ldg(&dst[e]);
    float w = g_alp2[e * 2 + h] / g_den2[d * 2 + h];
    float4 v = *(const float4*)&g_h2[s * C2T + q * 4];
    red4(&g_out2[d * C2T + q * 4], v.x * w, v.y * w, v.z * w, v.w * w);
}

// ---------------- layer-1 epilogue: self msg + bias + BN partial stats -------
__global__ void k_post1(const float* __restrict__ b1) {
    int c = threadIdx.x;                    // 128 threads, one per feature
    int i0 = blockIdx.x * 32;
    int head = c >> 6;
    float bias = b1[c];
    float s = 0.f, q = 0.f;
    for (int r = 0; r < 32; r++) {
        int i = i0 + r;
        if (i >= Nn) break;
        float w = __expf(g_aself1[i * 2 + head] - fdec(g_amax1[i * 2 + head])) / g_den1[i * 2 + head];
        float v = g_out1[i * F + c] + g_h1[i * F + c] * w + bias;
        g_out1[i * F + c] = v;
        s += v; q += v * v;
    }
    atomicAdd(&g_bns[c], s);
    atomicAdd(&g_bnq[c], q);
}

__global__ void k_bnf(const float* __restrict__ gamma, const float* __restrict__ beta) {
    int c = threadIdx.x;
    float m = g_bns[c] / (float)Nn;
    float v = g_bnq[c] / (float)Nn - m * m;
    float sc = gamma[c] * rsqrtf(v + EPS);
    g_scale[c] = sc;
    g_shift[c] = beta[c] - m * sc;
}

// ---------------- GEMM2: h2 = BN(out1) @ W2, fused attention dots ------------
__global__ __launch_bounds__(256)
void k_gemm2(const float* __restrict__ W, const float* __restrict__ attS,
             const float* __restrict__ attD) {
    __shared__ float xs[32][64];
    __shared__ float ws[32][C2T];
    __shared__ float sc[F], sh[F];
    int tid = threadIdx.x;
    if (tid < F) { sc[tid] = g_scale[tid]; sh[tid] = g_shift[tid]; }
    int rowBase = blockIdx.x * 64;
    int tx = tid & 15, ty = tid >> 4;
    float acc[4][5] = {};
    __syncthreads();

    for (int k0 = 0; k0 < F; k0 += 32) {
        #pragma unroll
        for (int l = 0; l < 2; l++) {
            int v = tid + l * 256;
            int r = v >> 3, kq = v & 7;
            int grow = rowBase + r;
            float4 xv = make_float4(0.f, 0.f, 0.f, 0.f);
            if (grow < Nn) xv = *(const float4*)&g_out1[grow * F + k0 + kq * 4];
            int kk = kq * 4;
            xs[kk + 0][r] = xv.x * sc[k0 + kk + 0] + sh[k0 + kk + 0];
            xs[kk + 1][r] = xv.y * sc[k0 + kk + 1] + sh[k0 + kk + 1];
            xs[kk + 2][r] = xv.z * sc[k0 + kk + 2] + sh[k0 + kk + 2];
            xs[kk + 3][r] = xv.w * sc[k0 + kk + 3] + sh[k0 + kk + 3];
        }
        #pragma unroll
        for (int l = 0; l < 3; l++) {       // 32*80 floats = 640 float4
            int v = tid + l * 256;
            if (v < 640) {
                int kk = v / 20, nq = v % 20;
                *(float4*)&ws[kk][nq * 4] = *(const float4*)&W[(k0 + kk) * C2T + nq * 4];
            }
        }
        __syncthreads();
        #pragma unroll
        for (int kk = 0; kk < 32; kk++) {
            float4 a = *(float4*)&xs[kk][ty * 4];
            float b[5];
            #pragma unroll
            for (int j = 0; j < 5; j++) b[j] = ws[kk][tx * 5 + j];
            #pragma unroll
            for (int j = 0; j < 5; j++) {
                acc[0][j] += a.x * b[j];
                acc[1][j] += a.y * b[j];
                acc[2][j] += a.z * b[j];
                acc[3][j] += a.w * b[j];
            }
        }
        __syncthreads();
    }
    int head = tx >> 3;                     // 5 cols per tx, head boundary at col 40
    #pragma unroll
    for (int r = 0; r < 4; r++) {
        int grow = rowBase + ty * 4 + r;
        if (grow < Nn) {
            float as = 0.f, ad = 0.f;
            #pragma unroll
            for (int j = 0; j < 5; j++) {
                int col = tx * 5 + j;
                g_h2[grow * C2T + col] = acc[r][j];
                as += acc[r][j] * attS[col];
                ad += acc[r][j] * attD[col];
            }
            atomicAdd(&g_asrc2[grow * 2 + head], as);
            atomicAdd(&g_adst2[grow * 2 + head], ad);
        }
    }
}

// ---------------- final: self msg + head mean + bias + log_softmax -----------
__global__ void k_final2(const float* __restrict__ b2, float* __restrict__ out) {
    int i = (blockIdx.x * blockDim.x + threadIdx.x) >> 5;
    int lane = threadIdx.x & 31;
    if (i >= Nn) return;
    float w0 = __expf(g_aself2[i * 2]     - fdec(g_amax2[i * 2]))     / g_den2[i * 2];
    float w1 = __expf(g_aself2[i * 2 + 1] - fdec(g_amax2[i * 2 + 1])) / g_den2[i * 2 + 1];
    const float* o  = &g_out2[i * C2T];
    const float* hh = &g_h2[i * C2T];

    int c = lane;                            // classes 0..31
    float va = 0.5f * ((o[c] + hh[c] * w0) + (o[40 + c] + hh[40 + c] * w1)) + b2[c];
    float vb = -1e30f;
    if (lane < 8) {                          // classes 32..39
        int cb = lane + 32;
        vb = 0.5f * ((o[cb] + hh[cb] * w0) + (o[40 + cb] + hh[40 + cb] * w1)) + b2[cb];
    }
    float m = fmaxf(va, vb);
    #pragma unroll
    for (int off = 16; off; off >>= 1) m = fmaxf(m, __shfl_xor_sync(0xffffffff, m, off));
    float s = __expf(va - m) + (lane < 8 ? __expf(vb - m) : 0.f);
    #pragma unroll
    for (int off = 16; off; off >>= 1) s += __shfl_xor_sync(0xffffffff, s, off);
    float lg = m + __logf(s);
    out[i * NCls + lane] = va - lg;
    if (lane < 8) out[i * NCls + 32 + lane] = vb - lg;
}

// ---------------- launch -----------------------------------------------------
extern "C" void kernel_launch(void* const* d_in, const int* in_sizes, int n_in,
                              void* d_out, int out_size) {
    const float* x     = (const float*)d_in[0];
    const int*   ei    = (const int*)  d_in[1];
    const float* W1    = (const float*)d_in[2];
    const float* as1   = (const float*)d_in[3];
    const float* ad1   = (const float*)d_in[4];
    const float* b1    = (const float*)d_in[5];
    const float* gamma = (const float*)d_in[6];
    const float* beta  = (const float*)d_in[7];
    const float* W2    = (const float*)d_in[8];
    const float* as2   = (const float*)d_in[9];
    const float* ad2   = (const float*)d_in[10];
    const float* b2    = (const float*)d_in[11];
    float* out = (float*)d_out;

    const int* src = ei;
    const int* dst = ei + Ee;

    const int TB = 256;
    int gN2 = (2 * Nn + TB - 1) / TB;
    int gE2 = (2 * Ee + TB - 1) / TB;

    k_zero<<<2048, TB>>>();
    k_gemm1<<<(Nn + 63) / 64, TB>>>(x, W1, as1, ad1);

    k_pre<1><<<gN2, TB>>>();
    k_emax<1><<<gE2, TB>>>(src, dst);
    k_mid<1><<<gN2, TB>>>();
    k_esum<1><<<gE2, TB>>>(dst);
    k_msg1<<<(Ee * 32 + TB - 1) / TB, TB>>>(src, dst);
    k_post1<<<(Nn + 31) / 32, 128>>>(b1);
    k_bnf<<<1, 128>>>(gamma, beta);

    k_gemm2<<<(Nn + 63) / 64, TB>>>(W2, as2, ad2);
    k_pre<2><<<gN2, TB>>>();
    k_emax<2><<<gE2, TB>>>(src, dst);
    k_mid<2><<<gN2, TB>>>();
    k_esum<2><<<gE2, TB>>>(dst);
    k_msg2<<<(Ee * 20 + TB - 1) / TB, TB>>>(src, dst);
    k_final2<<<(Nn * 32 + TB - 1) / TB, TB>>>(b2, out);
}

// round 7
// speedup vs baseline: 1.6203x; 1.6203x over previous
#include <cuda_runtime.h>

#define Nn   100000
#define Ee   1600000
#define F    128          // IN_F == HIDDEN
#define C2T  80           // HEADS * N_CLASSES
#define NCls 40
#define NEG  0.2f
#define EPS  1e-5f

// ---------------- scratch (static device globals; no runtime alloc) ----------
__device__ __align__(16) float g_h1[Nn * F];
__device__ __align__(16) float g_out1[Nn * F];
__device__ __align__(16) float g_h2[Nn * C2T];
__device__ __align__(16) float g_out2[Nn * C2T];

__device__ __align__(16) float g_asrc1[Nn * 2], g_adst1[Nn * 2], g_aself1[Nn * 2], g_den1[Nn * 2];
__device__ __align__(16) float g_asrc2[Nn * 2], g_adst2[Nn * 2], g_aself2[Nn * 2], g_den2[Nn * 2];

__device__ float g_bns[F], g_bnq[F], g_scale[F], g_shift[F];

// ---------------- helpers ----------------------------------------------------
__device__ __forceinline__ float lrelu(float x){ return x > 0.f ? x : NEG * x; }

__device__ __forceinline__ void red4(float* p, float a, float b, float c, float d) {
    asm volatile("red.global.add.v4.f32 [%0], {%1,%2,%3,%4};"
                 :: "l"(p), "f"(a), "f"(b), "f"(c), "f"(d) : "memory");
}
__device__ __forceinline__ void red2(float* p, float a, float b) {
    asm volatile("red.global.add.v2.f32 [%0], {%1,%2};"
                 :: "l"(p), "f"(a), "f"(b) : "memory");
}
__device__ __forceinline__ unsigned f2tf32(float f) {
    unsigned u;
    asm("cvt.rna.tf32.f32 %0, %1;" : "=r"(u) : "f"(f));
    return u;
}
__device__ __forceinline__ void mma_tf32(float* d, const unsigned* a, const unsigned* b) {
    asm volatile(
        "mma.sync.aligned.m16n8k8.row.col.f32.tf32.tf32.f32 "
        "{%0,%1,%2,%3}, {%4,%5,%6,%7}, {%8,%9}, {%0,%1,%2,%3};\n"
        : "+f"(d[0]), "+f"(d[1]), "+f"(d[2]), "+f"(d[3])
        : "r"(a[0]), "r"(a[1]), "r"(a[2]), "r"(a[3]), "r"(b[0]), "r"(b[1]));
}

template<int L> __device__ __forceinline__ float* P_asrc()  { return L == 1 ? g_asrc1  : g_asrc2;  }
template<int L> __device__ __forceinline__ float* P_adst()  { return L == 1 ? g_adst1  : g_adst2;  }
template<int L> __device__ __forceinline__ float* P_aself() { return L == 1 ? g_aself1 : g_aself2; }
template<int L> __device__ __forceinline__ float* P_den()   { return L == 1 ? g_den1   : g_den2;   }

// ================= GEMM1: h1 = x @ W1 (tf32 tensor cores) ====================
// block 256 thr = 8 warps; block tile 128x128; warp tile 32(M) x 64(N)
__global__ __launch_bounds__(256)
void k_gemm1(const float* __restrict__ x, const float* __restrict__ W,
             const float* __restrict__ attS, const float* __restrict__ attD) {
    __shared__ unsigned As[128][36];    // pad 36: A-frag reads conflict-free
    __shared__ unsigned Bs[32][136];    // pad 136: B-frag reads conflict-free
    int tid  = threadIdx.x;
    int lane = tid & 31, wid = tid >> 5;
    int warpM = wid & 3, warpN = wid >> 2;   // 4 x 2
    int g = lane >> 2, tig = lane & 3;
    int rowBase = blockIdx.x * 128;
    float acc[2][8][4] = {};

    for (int k0 = 0; k0 < F; k0 += 32) {
        #pragma unroll
        for (int l = 0; l < 4; l++) {               // A tile 128x32
            int v = tid + l * 256;
            int r = v >> 3, kq = v & 7;
            int grow = rowBase + r;
            float4 xv = make_float4(0.f, 0.f, 0.f, 0.f);
            if (grow < Nn) xv = *(const float4*)&x[grow * F + k0 + kq * 4];
            As[r][kq*4+0] = f2tf32(xv.x); As[r][kq*4+1] = f2tf32(xv.y);
            As[r][kq*4+2] = f2tf32(xv.z); As[r][kq*4+3] = f2tf32(xv.w);
        }
        #pragma unroll
        for (int l = 0; l < 4; l++) {               // B tile 32x128
            int v = tid + l * 256;
            int kk = v >> 5, nq = v & 31;
            float4 wv = *(const float4*)&W[(k0 + kk) * F + nq * 4];
            Bs[kk][nq*4+0] = f2tf32(wv.x); Bs[kk][nq*4+1] = f2tf32(wv.y);
            Bs[kk][nq*4+2] = f2tf32(wv.z); Bs[kk][nq*4+3] = f2tf32(wv.w);
        }
        __syncthreads();
        #pragma unroll
        for (int ks = 0; ks < 4; ks++) {
            unsigned a[2][4];
            #pragma unroll
            for (int mi = 0; mi < 2; mi++) {
                int r = warpM * 32 + mi * 16 + g;
                a[mi][0] = As[r    ][ks*8 + tig];
                a[mi][1] = As[r + 8][ks*8 + tig];
                a[mi][2] = As[r    ][ks*8 + tig + 4];
                a[mi][3] = As[r + 8][ks*8 + tig + 4];
            }
            #pragma unroll
            for (int ni = 0; ni < 8; ni++) {
                unsigned b[2];
                int c = warpN * 64 + ni * 8 + g;
                b[0] = Bs[ks*8 + tig    ][c];
                b[1] = Bs[ks*8 + tig + 4][c];
                mma_tf32(acc[0][ni], a[0], b);
                mma_tf32(acc[1][ni], a[1], b);
            }
        }
        __syncthreads();
    }

    // epilogue: store h1 + fused attention dots (non-atomic via quad reduce)
    #pragma unroll
    for (int mi = 0; mi < 2; mi++) {
        int r0 = rowBase + warpM * 32 + mi * 16 + g;
        int r1 = r0 + 8;
        float as0 = 0.f, ad0 = 0.f, as1 = 0.f, ad1 = 0.f;
        #pragma unroll
        for (int ni = 0; ni < 8; ni++) {
            int c0 = warpN * 64 + ni * 8 + 2 * tig;
            float sa = __ldg(&attS[c0]), sb = __ldg(&attS[c0 + 1]);
            float da = __ldg(&attD[c0]), db = __ldg(&attD[c0 + 1]);
            as0 += acc[mi][ni][0] * sa + acc[mi][ni][1] * sb;
            ad0 += acc[mi][ni][0] * da + acc[mi][ni][1] * db;
            as1 += acc[mi][ni][2] * sa + acc[mi][ni][3] * sb;
            ad1 += acc[mi][ni][2] * da + acc[mi][ni][3] * db;
            if (r0 < Nn) *(float2*)&g_h1[r0 * F + c0] = make_float2(acc[mi][ni][0], acc[mi][ni][1]);
            if (r1 < Nn) *(float2*)&g_h1[r1 * F + c0] = make_float2(acc[mi][ni][2], acc[mi][ni][3]);
        }
        as0 += __shfl_xor_sync(0xffffffff, as0, 1); as0 += __shfl_xor_sync(0xffffffff, as0, 2);
        ad0 += __shfl_xor_sync(0xffffffff, ad0, 1); ad0 += __shfl_xor_sync(0xffffffff, ad0, 2);
        as1 += __shfl_xor_sync(0xffffffff, as1, 1); as1 += __shfl_xor_sync(0xffffffff, as1, 2);
        ad1 += __shfl_xor_sync(0xffffffff, ad1, 1); ad1 += __shfl_xor_sync(0xffffffff, ad1, 2);
        if (tig == 0) {
            if (r0 < Nn) { g_asrc1[r0 * 2 + warpN] = as0; g_adst1[r0 * 2 + warpN] = ad0; }
            if (r1 < Nn) { g_asrc1[r1 * 2 + warpN] = as1; g_adst1[r1 * 2 + warpN] = ad1; }
        }
    }
}

// ================= GEMM2: h2 = BN(out1) @ W2 (tf32) ==========================
// block tile 128x80; warp tile 32(M) x 40(N); head boundary == warpN boundary
__global__ __launch_bounds__(256)
void k_gemm2(const float* __restrict__ W, const float* __restrict__ attS,
             const float* __restrict__ attD) {
    __shared__ unsigned As[128][36];
    __shared__ unsigned Bs[32][88];
    __shared__ float sc[F], sh[F];
    int tid  = threadIdx.x;
    int lane = tid & 31, wid = tid >> 5;
    int warpM = wid & 3, warpN = wid >> 2;
    int g = lane >> 2, tig = lane & 3;
    int rowBase = blockIdx.x * 128;
    float acc[2][5][4] = {};

    if (tid < F) { sc[tid] = g_scale[tid]; sh[tid] = g_shift[tid]; }
    __syncthreads();

    for (int k0 = 0; k0 < F; k0 += 32) {
        #pragma unroll
        for (int l = 0; l < 4; l++) {               // A tile, BN applied at load
            int v = tid + l * 256;
            int r = v >> 3, kq = v & 7;
            int grow = rowBase + r;
            float4 xv = make_float4(0.f, 0.f, 0.f, 0.f);
            if (grow < Nn) xv = *(const float4*)&g_out1[grow * F + k0 + kq * 4];
            int kc = k0 + kq * 4;
            As[r][kq*4+0] = f2tf32(xv.x * sc[kc+0] + sh[kc+0]);
            As[r][kq*4+1] = f2tf32(xv.y * sc[kc+1] + sh[kc+1]);
            As[r][kq*4+2] = f2tf32(xv.z * sc[kc+2] + sh[kc+2]);
            As[r][kq*4+3] = f2tf32(xv.w * sc[kc+3] + sh[kc+3]);
        }
        #pragma unroll
        for (int l = 0; l < 3; l++) {               // B tile 32x80 = 640 float4
            int v = tid + l * 256;
            if (v < 640) {
                int kk = v / 20, nq = v % 20;
                float4 wv = *(const float4*)&W[(k0 + kk) * C2T + nq * 4];
                Bs[kk][nq*4+0] = f2tf32(wv.x); Bs[kk][nq*4+1] = f2tf32(wv.y);
                Bs[kk][nq*4+2] = f2tf32(wv.z); Bs[kk][nq*4+3] = f2tf32(wv.w);
            }
        }
        __syncthreads();
        #pragma unroll
        for (int ks = 0; ks < 4; ks++) {
            unsigned a[2][4];
            #pragma unroll
            for (int mi = 0; mi < 2; mi++) {
                int r = warpM * 32 + mi * 16 + g;
                a[mi][0] = As[r    ][ks*8 + tig];
                a[mi][1] = As[r + 8][ks*8 + tig];
                a[mi][2] = As[r    ][ks*8 + tig + 4];
                a[mi][3] = As[r + 8][ks*8 + tig + 4];
            }
            #pragma unroll
            for (int ni = 0; ni < 5; ni++) {
                unsigned b[2];
                int c = warpN * 40 + ni * 8 + g;
                b[0] = Bs[ks*8 + tig    ][c];
                b[1] = Bs[ks*8 + tig + 4][c];
                mma_tf32(acc[0][ni], a[0], b);
                mma_tf32(acc[1][ni], a[1], b);
            }
        }
        __syncthreads();
    }

    #pragma unroll
    for (int mi = 0; mi < 2; mi++) {
        int r0 = rowBase + warpM * 32 + mi * 16 + g;
        int r1 = r0 + 8;
        float as0 = 0.f, ad0 = 0.f, as1 = 0.f, ad1 = 0.f;
        #pragma unroll
        for (int ni = 0; ni < 5; ni++) {
            int c0 = warpN * 40 + ni * 8 + 2 * tig;
            float sa = __ldg(&attS[c0]), sb = __ldg(&attS[c0 + 1]);
            float da = __ldg(&attD[c0]), db = __ldg(&attD[c0 + 1]);
            as0 += acc[mi][ni][0] * sa + acc[mi][ni][1] * sb;
            ad0 += acc[mi][ni][0] * da + acc[mi][ni][1] * db;
            as1 += acc[mi][ni][2] * sa + acc[mi][ni][3] * sb;
            ad1 += acc[mi][ni][2] * da + acc[mi][ni][3] * db;
            if (r0 < Nn) *(float2*)&g_h2[r0 * C2T + c0] = make_float2(acc[mi][ni][0], acc[mi][ni][1]);
            if (r1 < Nn) *(float2*)&g_h2[r1 * C2T + c0] = make_float2(acc[mi][ni][2], acc[mi][ni][3]);
        }
        as0 += __shfl_xor_sync(0xffffffff, as0, 1); as0 += __shfl_xor_sync(0xffffffff, as0, 2);
        ad0 += __shfl_xor_sync(0xffffffff, ad0, 1); ad0 += __shfl_xor_sync(0xffffffff, ad0, 2);
        as1 += __shfl_xor_sync(0xffffffff, as1, 1); as1 += __shfl_xor_sync(0xffffffff, as1, 2);
        ad1 += __shfl_xor_sync(0xffffffff, ad1, 1); ad1 += __shfl_xor_sync(0xffffffff, ad1, 2);
        if (tig == 0) {
            if (r0 < Nn) { g_asrc2[r0 * 2 + warpN] = as0; g_adst2[r0 * 2 + warpN] = ad0; }
            if (r1 < Nn) { g_asrc2[r1 * 2 + warpN] = as1; g_adst2[r1 * 2 + warpN] = ad1; }
        }
    }
}

// ================= attention pipeline (no max-shift; softmax shift-invariant) =
template<int L>
__global__ void k_pre() {                 // e_self = exp(alpha_self); seed denom
    int t = blockIdx.x * blockDim.x + threadIdx.x;
    if (L == 1 && t < F) { g_bns[t] = 0.f; g_bnq[t] = 0.f; }
    if (t >= 2 * Nn) return;
    float e = __expf(lrelu(P_asrc<L>()[t] + P_adst<L>()[t]));
    P_aself<L>()[t] = e;
    P_den<L>()[t]   = e;
}

template<int L>
__global__ void k_esum(const int* __restrict__ src, const int* __restrict__ dst) {
    int e = blockIdx.x * blockDim.x + threadIdx.x;
    if (e >= Ee) return;
    int s = __ldg(&src[e]), d = __ldg(&dst[e]);
    float e0 = __expf(lrelu(P_asrc<L>()[s * 2]     + P_adst<L>()[d * 2]));
    float e1 = __expf(lrelu(P_asrc<L>()[s * 2 + 1] + P_adst<L>()[d * 2 + 1]));
    red2(&P_den<L>()[d * 2], e0, e1);
}

template<int L>
__global__ void k_rinv() {                // den -> 1/den
    int t = blockIdx.x * blockDim.x + threadIdx.x;
    if (t >= 2 * Nn) return;
    P_den<L>()[t] = 1.0f / P_den<L>()[t];
}

// init out = self message (replaces zeroing + post-pass self add)
__global__ void k_init1() {
    int t = blockIdx.x * blockDim.x + threadIdx.x;
    if (t >= Nn * 32) return;
    int i = t >> 5, q = t & 31, h = q >> 4;
    float w = g_aself1[i * 2 + h] * g_den1[i * 2 + h];
    float4 v = ((const float4*)g_h1)[t];
    ((float4*)g_out1)[t] = make_float4(v.x * w, v.y * w, v.z * w, v.w * w);
}
__global__ void k_init2() {
    int t = blockIdx.x * blockDim.x + threadIdx.x;
    if (t >= Nn * 20) return;
    int i = t / 20, q = t % 20, h = q / 10;
    float w = g_aself2[i * 2 + h] * g_den2[i * 2 + h];
    float4 v = ((const float4*)g_h2)[t];
    ((float4*)g_out2)[t] = make_float4(v.x * w, v.y * w, v.z * w, v.w * w);
}

// ---------------- edge messages: layer 1 (warp per edge, 128 floats) ---------
__global__ void k_msg1(const int* __restrict__ src, const int* __restrict__ dst) {
    int warp = (blockIdx.x * blockDim.x + threadIdx.x) >> 5;
    int lane = threadIdx.x & 31;
    if (warp >= Ee) return;
    int s = __ldg(&src[warp]);
    int d = __ldg(&dst[warp]);
    int h = lane >> 4;
    float w = __expf(lrelu(g_asrc1[s * 2 + h] + g_adst1[d * 2 + h])) * g_den1[d * 2 + h];
    float4 v = ((const float4*)&g_h1[s * F])[lane];
    red4(&g_out1[d * F + lane * 4], v.x * w, v.y * w, v.z * w, v.w * w);
}

// ---------------- edge messages: layer 2 (20 threads per edge, 80 floats) ----
__global__ void k_msg2(const int* __restrict__ src, const int* __restrict__ dst) {
    int t = blockIdx.x * blockDim.x + threadIdx.x;
    if (t >= Ee * 20) return;
    int e = t / 20, q = t % 20;
    int h = q / 10;
    int s = __ldg(&src[e]);
    int d = __ldg(&dst[e]);
    float w = __expf(lrelu(g_asrc2[s * 2 + h] + g_adst2[d * 2 + h])) * g_den2[d * 2 + h];
    float4 v = *(const float4*)&g_h2[s * C2T + q * 4];
    red4(&g_out2[d * C2T + q * 4], v.x * w, v.y * w, v.z * w, v.w * w);
}

// ---------------- BN stats (b1 cancels inside BatchNorm) ---------------------
__global__ void k_stats() {
    int c = threadIdx.x;                    // 128 threads, one per feature
    int i0 = blockIdx.x * 64;
    float s = 0.f, q = 0.f;
    for (int r = 0; r < 64; r++) {
        int i = i0 + r;
        if (i >= Nn) break;
        float v = g_out1[i * F + c];
        s += v; q += v * v;
    }
    atomicAdd(&g_bns[c], s);
    atomicAdd(&g_bnq[c], q);
}

__global__ void k_bnf(const float* __restrict__ gamma, const float* __restrict__ beta) {
    int c = threadIdx.x;
    float m = g_bns[c] / (float)Nn;
    float v = g_bnq[c] / (float)Nn - m * m;
    float sc = gamma[c] * rsqrtf(v + EPS);
    g_scale[c] = sc;
    g_shift[c] = beta[c] - m * sc;
}

// ---------------- final: head mean + bias + log_softmax ----------------------
__global__ void k_final2(const float* __restrict__ b2, float* __restrict__ out) {
    int i = (blockIdx.x * blockDim.x + threadIdx.x) >> 5;
    int lane = threadIdx.x & 31;
    if (i >= Nn) return;
    const float* o = &g_out2[i * C2T];

    int c = lane;                            // classes 0..31
    float va = 0.5f * (o[c] + o[40 + c]) + __ldg(&b2[c]);
    float vb = -1e30f;
    if (lane < 8) {
        int cb = lane + 32;
        vb = 0.5f * (o[cb] + o[40 + cb]) + __ldg(&b2[cb]);
    }
    float m = fmaxf(va, vb);
    #pragma unroll
    for (int off = 16; off; off >>= 1) m = fmaxf(m, __shfl_xor_sync(0xffffffff, m, off));
    float s = __expf(va - m) + (lane < 8 ? __expf(vb - m) : 0.f);
    #pragma unroll
    for (int off = 16; off; off >>= 1) s += __shfl_xor_sync(0xffffffff, s, off);
    float lg = m + __logf(s);
    out[i * NCls + lane] = va - lg;
    if (lane < 8) out[i * NCls + 32 + lane] = vb - lg;
}

// ---------------- launch -----------------------------------------------------
extern "C" void kernel_launch(void* const* d_in, const int* in_sizes, int n_in,
                              void* d_out, int out_size) {
    const float* x     = (const float*)d_in[0];
    const int*   ei    = (const int*)  d_in[1];
    const float* W1    = (const float*)d_in[2];
    const float* as1   = (const float*)d_in[3];
    const float* ad1   = (const float*)d_in[4];
    // d_in[5] = b1 (cancels inside BatchNorm — unused)
    const float* gamma = (const float*)d_in[6];
    const float* beta  = (const float*)d_in[7];
    const float* W2    = (const float*)d_in[8];
    const float* as2   = (const float*)d_in[9];
    const float* ad2   = (const float*)d_in[10];
    const float* b2    = (const float*)d_in[11];
    float* out = (float*)d_out;

    const int* src = ei;
    const int* dst = ei + Ee;

    const int TB = 256;
    int gN2 = (2 * Nn + TB - 1) / TB;
    int gE  = (Ee + TB - 1) / TB;
    int gG  = (Nn + 127) / 128;

    // ---- layer 1 ----
    k_gemm1<<<gG, TB>>>(x, W1, as1, ad1);
    k_pre<1><<<gN2, TB>>>();
    k_esum<1><<<gE, TB>>>(src, dst);
    k_rinv<1><<<gN2, TB>>>();
    k_init1<<<(Nn * 32 + TB - 1) / TB, TB>>>();
    k_msg1<<<(Ee * 32 + TB - 1) / TB, TB>>>(src, dst);
    k_stats<<<(Nn + 63) / 64, 128>>>();
    k_bnf<<<1, 128>>>(gamma, beta);

    // ---- layer 2 ----
    k_gemm2<<<gG, TB>>>(W2, as2, ad2);
    k_pre<2><<<gN2, TB>>>();
    k_esum<2><<<gE, TB>>>(src, dst);
    k_rinv<2><<<gN2, TB>>>();
    k_init2<<<(Nn * 20 + TB - 1) / TB, TB>>>();
    k_msg2<<<(Ee * 20 + TB - 1) / TB, TB>>>(src, dst);
    k_final2<<<(Nn * 32 + TB - 1) / TB, TB>>>(b2, out);
}